// round 1
// baseline (speedup 1.0000x reference)
#include <cuda_runtime.h>
#include <cuda_bf16.h>

// ProposalTarget: B=16, A=9, H=W=128, S=2048 (fixed by setup_inputs).
// Output: (B, A, H, W, 9) float32 = 21,233,664 elements.
//
// out[..., 0:4] = proposal (ltx,lty,rbx,rby) * m
// out[..., 4:8] = rpn_box  (cx,cy,w,h) / S * m
// out[..., 8]   = m
//
// HBM-bound: ~142 MB total traffic. Key optimizations:
//  - anchor table (depends only on (a, w)) preloaded to smem per block
//  - output staged in smem, flushed as coalesced float4 stores

#define B_   16
#define A_   9
#define H_   128
#define W_   128
#define HW_  (H_ * W_)            // 16384
#define NTOT (B_ * A_ * HW_)      // 2359296
#define TPB  256
#define OUT_PER_BLK (TPB * 9)     // 2304 floats per block

__global__ __launch_bounds__(TPB)
void proposal_target_kernel(const float* __restrict__ cla_map,
                            const float* __restrict__ reg_map,
                            const float* __restrict__ anchor,
                            float* __restrict__ out)
{
    __shared__ float4 s_anc[W_];          // (acx, acy, aw, ah) per w for this block's a
    __shared__ float  s_out[OUT_PER_BLK]; // staged output

    const int tid = threadIdx.x;
    const int i   = blockIdx.x * TPB + tid;   // linear (b,a,h,w)

    // Block-uniform anchor index 'a' (TPB=256 divides HW=16384, so one (b,a) per block)
    const int a_blk = (int)((blockIdx.x * TPB) >> 14) % A_;

    // Preload anchors: row = w * 129 * a ; want cols 2..5
    if (tid < W_) {
        const int row = tid * 129 * a_blk;              // <= 131064
        const float* p = anchor + (size_t)row * 6 + 2;
        s_anc[tid] = make_float4(__ldg(p + 0), __ldg(p + 1), __ldg(p + 2), __ldg(p + 3));
    }
    __syncthreads();

    // Decode indices
    const int w  = i & (W_ - 1);
    const int hw = i & (HW_ - 1);
    const int a  = a_blk;
    const int b  = i / (A_ * HW_);

    // Loads (fully coalesced: consecutive threads = consecutive w)
    const size_t cla_base = ((size_t)(b * (2 * A_) + 2 * a)) * HW_ + hw;
    const float c0 = __ldg(cla_map + cla_base);
    const float c1 = __ldg(cla_map + cla_base + HW_);

    const size_t reg_base = ((size_t)(b * (4 * A_) + 4 * a)) * HW_ + hw;
    const float tx = __ldg(reg_map + reg_base);
    const float ty = __ldg(reg_map + reg_base + HW_);
    const float tw = __ldg(reg_map + reg_base + 2 * HW_);
    const float th = __ldg(reg_map + reg_base + 3 * HW_);

    const float4 anc = s_anc[w];
    const float acx = anc.x, acy = anc.y, aw = anc.z, ah = anc.w;

    const float S    = 2048.0f;
    const float invS = 1.0f / 2048.0f;

    // fg = softmax(cla, axis=2)[:,:,1] = sigmoid(c1 - c0)
    const float fg = 1.0f / (1.0f + expf(c0 - c1));

    const float cx = (tx * aw + acx) * S;
    const float cy = (ty * ah + acy) * S;
    const float wd = expf(tw) * aw * S;
    const float hd = expf(th) * ah * S;

    const float ltx = cx - 0.5f * wd;
    const float lty = cy - 0.5f * hd;
    const float rbx = cx + 0.5f * wd;
    const float rby = cy + 0.5f * hd;

    const bool valid = (fg > 0.7f) & (ltx >= 0.0f) & (lty >= 0.0f)
                     & (rbx <= S)  & (rby <= S);
    const float m = valid ? 1.0f : 0.0f;
    const float mS = m * invS;

    // Stage into smem: stride-9 writes, gcd(9,32)=1 -> bank-conflict-free
    float* sp = s_out + tid * 9;
    sp[0] = ltx * m;
    sp[1] = lty * m;
    sp[2] = rbx * m;
    sp[3] = rby * m;
    sp[4] = cx * mS;
    sp[5] = cy * mS;
    sp[6] = wd * mS;
    sp[7] = hd * mS;
    sp[8] = m;
    __syncthreads();

    // Coalesced flush: 2304 floats = 576 float4 per block; block base is 16B aligned
    float4*       dst = reinterpret_cast<float4*>(out + (size_t)blockIdx.x * OUT_PER_BLK);
    const float4* src = reinterpret_cast<const float4*>(s_out);
    #pragma unroll
    for (int j = tid; j < OUT_PER_BLK / 4; j += TPB) {
        dst[j] = src[j];
    }
}

extern "C" void kernel_launch(void* const* d_in, const int* in_sizes, int n_in,
                              void* d_out, int out_size)
{
    const float* cla_map = (const float*)d_in[0];
    const float* reg_map = (const float*)d_in[1];
    const float* anchor  = (const float*)d_in[2];
    float*       out     = (float*)d_out;

    const int grid = NTOT / TPB;   // 9216
    proposal_target_kernel<<<grid, TPB>>>(cla_map, reg_map, anchor, out);
}

// round 2
// speedup vs baseline: 1.0078x; 1.0078x over previous
#include <cuda_runtime.h>
#include <cuda_bf16.h>

// ProposalTarget: B=16, A=9, H=W=128, S=2048 (fixed).
// Output: (B, A, H, W, 9) float32.
//
// R1 finding: kernel was LSU-instruction-bound (19.5 mem instr/elem, L1=69%).
// R2: 4 elements per thread, all 128-bit memory ops -> 8.25 mem instr/elem.

#define B_   16
#define A_   9
#define H_   128
#define W_   128
#define HW_  (H_ * W_)            // 16384
#define AHW_ (A_ * HW_)           // 147456
#define NTOT (B_ * AHW_)          // 2359296
#define TPB  256
#define VEC  4
#define ELEMS_PER_BLK (TPB * VEC)         // 1024
#define OUT_F_PER_BLK (ELEMS_PER_BLK * 9) // 9216 floats
#define OUT_V_PER_BLK (OUT_F_PER_BLK / 4) // 2304 float4

__global__ __launch_bounds__(TPB)
void proposal_target_kernel(const float* __restrict__ cla_map,
                            const float* __restrict__ reg_map,
                            const float* __restrict__ anchor,
                            float* __restrict__ out)
{
    __shared__ float4 s_anc[W_];              // (acx,acy,aw,ah) per w, block-uniform a
    __shared__ float4 s_out[OUT_V_PER_BLK];   // 36 KB staged output

    const int tid = threadIdx.x;

    // Block-uniform (b, a): ELEMS_PER_BLK=1024 divides HW=16384
    const int a_blk = (blockIdx.x >> 4) % A_;          // (blk*1024)/16384 % 9
    const int b_blk = blockIdx.x / (AHW_ / ELEMS_PER_BLK); // blk/144

    // Preload anchors for this a: row = w * 129 * a, cols 2..5
    if (tid < W_) {
        const int row = tid * 129 * a_blk;
        const float* p = anchor + (size_t)row * 6 + 2;
        s_anc[tid] = make_float4(__ldg(p + 0), __ldg(p + 1), __ldg(p + 2), __ldg(p + 3));
    }
    __syncthreads();

    const int i0 = blockIdx.x * ELEMS_PER_BLK + tid * VEC; // first of 4 consecutive elems
    const int hw = i0 & (HW_ - 1);
    const int w0 = i0 & (W_ - 1);                           // w0..w0+3 (no wrap: w0%4==0)

    // 128-bit input loads (all 16B aligned: hw % 4 == 0)
    const size_t cla_base = ((size_t)(b_blk * (2 * A_) + 2 * a_blk)) * HW_ + hw;
    const float4 c0v = *reinterpret_cast<const float4*>(cla_map + cla_base);
    const float4 c1v = *reinterpret_cast<const float4*>(cla_map + cla_base + HW_);

    const size_t reg_base = ((size_t)(b_blk * (4 * A_) + 4 * a_blk)) * HW_ + hw;
    const float4 txv = *reinterpret_cast<const float4*>(reg_map + reg_base);
    const float4 tyv = *reinterpret_cast<const float4*>(reg_map + reg_base + HW_);
    const float4 twv = *reinterpret_cast<const float4*>(reg_map + reg_base + 2 * HW_);
    const float4 thv = *reinterpret_cast<const float4*>(reg_map + reg_base + 3 * HW_);

    const float S    = 2048.0f;
    const float invS = 1.0f / 2048.0f;

    float vout[VEC * 9];   // 36 floats, fully unrolled -> registers

    const float* c0a = &c0v.x; const float* c1a = &c1v.x;
    const float* txa = &txv.x; const float* tya = &tyv.x;
    const float* twa = &twv.x; const float* tha = &thv.x;

    #pragma unroll
    for (int e = 0; e < VEC; e++) {
        const float4 anc = s_anc[w0 + e];
        const float acx = anc.x, acy = anc.y, aw = anc.z, ah = anc.w;

        // fg = softmax over 2 = sigmoid(c1 - c0)
        const float fg = 1.0f / (1.0f + expf(c0a[e] - c1a[e]));

        const float cx = (txa[e] * aw + acx) * S;
        const float cy = (tya[e] * ah + acy) * S;
        const float wd = expf(twa[e]) * aw * S;
        const float hd = expf(tha[e]) * ah * S;

        const float ltx = cx - 0.5f * wd;
        const float lty = cy - 0.5f * hd;
        const float rbx = cx + 0.5f * wd;
        const float rby = cy + 0.5f * hd;

        const bool valid = (fg > 0.7f) & (ltx >= 0.0f) & (lty >= 0.0f)
                         & (rbx <= S)  & (rby <= S);
        const float m  = valid ? 1.0f : 0.0f;
        const float mS = m * invS;

        vout[e * 9 + 0] = ltx * m;
        vout[e * 9 + 1] = lty * m;
        vout[e * 9 + 2] = rbx * m;
        vout[e * 9 + 3] = rby * m;
        vout[e * 9 + 4] = cx * mS;
        vout[e * 9 + 5] = cy * mS;
        vout[e * 9 + 6] = wd * mS;
        vout[e * 9 + 7] = hd * mS;
        vout[e * 9 + 8] = m;
    }

    // Stage: 9 x STS.128 at float4 index tid*9 (byte offset tid*144, 16B aligned,
    // bank-conflict-free: phase lanes hit disjoint 4-bank groups)
    {
        float4* sp = s_out + tid * 9;
        const float4* vp = reinterpret_cast<const float4*>(vout);
        #pragma unroll
        for (int j = 0; j < 9; j++) sp[j] = vp[j];
    }
    __syncthreads();

    // Coalesced flush: 2304 float4 per block, 9 per thread
    float4* dst = reinterpret_cast<float4*>(out + (size_t)blockIdx.x * OUT_F_PER_BLK);
    #pragma unroll
    for (int j = 0; j < 9; j++) {
        const int k = j * TPB + tid;
        dst[k] = s_out[k];
    }
}

extern "C" void kernel_launch(void* const* d_in, const int* in_sizes, int n_in,
                              void* d_out, int out_size)
{
    const float* cla_map = (const float*)d_in[0];
    const float* reg_map = (const float*)d_in[1];
    const float* anchor  = (const float*)d_in[2];
    float*       out     = (float*)d_out;

    const int grid = NTOT / ELEMS_PER_BLK;   // 2304
    proposal_target_kernel<<<grid, TPB>>>(cla_map, reg_map, anchor, out);
}

// round 3
// speedup vs baseline: 1.0354x; 1.0274x over previous
#include <cuda_runtime.h>
#include <cuda_bf16.h>
#include <cstdint>

// ProposalTarget: B=16, A=9, H=W=128, S=2048 (fixed).
// R2 finding: latency-bound; no unit saturated; flush phase (LDS+STG) wastes
// SM issue slots. R3: offload the 36KB/CTA contiguous output flush to the TMA
// engine via cp.async.bulk (1D bulk store), SM does only LDG + STS.

#define B_   16
#define A_   9
#define H_   128
#define W_   128
#define HW_  (H_ * W_)            // 16384
#define AHW_ (A_ * HW_)           // 147456
#define NTOT (B_ * AHW_)          // 2359296
#define TPB  256
#define VEC  4
#define ELEMS_PER_BLK (TPB * VEC)         // 1024
#define OUT_F_PER_BLK (ELEMS_PER_BLK * 9) // 9216 floats
#define OUT_V_PER_BLK (OUT_F_PER_BLK / 4) // 2304 float4
#define OUT_BYTES_PER_BLK (OUT_F_PER_BLK * 4)  // 36864

__device__ __forceinline__ uint32_t smem_u32(const void* p) {
    return (uint32_t)__cvta_generic_to_shared(p);
}

__global__ __launch_bounds__(TPB)
void proposal_target_kernel(const float* __restrict__ cla_map,
                            const float* __restrict__ reg_map,
                            const float* __restrict__ anchor,
                            float* __restrict__ out)
{
    __shared__ float4 s_anc[W_];                          // anchors for block's a
    __shared__ __align__(128) float4 s_out[OUT_V_PER_BLK]; // 36 KB staged output

    const int tid = threadIdx.x;

    // Block-uniform (b, a): ELEMS_PER_BLK=1024 divides HW=16384
    const int a_blk = (blockIdx.x >> 4) % A_;
    const int b_blk = blockIdx.x / (AHW_ / ELEMS_PER_BLK);

    // Preload anchors: row = w * 129 * a, cols 2..5
    if (tid < W_) {
        const int row = tid * 129 * a_blk;
        const float* p = anchor + (size_t)row * 6 + 2;
        s_anc[tid] = make_float4(__ldg(p + 0), __ldg(p + 1), __ldg(p + 2), __ldg(p + 3));
    }
    __syncthreads();

    const int i0 = blockIdx.x * ELEMS_PER_BLK + tid * VEC;
    const int hw = i0 & (HW_ - 1);
    const int w0 = i0 & (W_ - 1);

    // 128-bit coalesced input loads
    const size_t cla_base = ((size_t)(b_blk * (2 * A_) + 2 * a_blk)) * HW_ + hw;
    const float4 c0v = *reinterpret_cast<const float4*>(cla_map + cla_base);
    const float4 c1v = *reinterpret_cast<const float4*>(cla_map + cla_base + HW_);

    const size_t reg_base = ((size_t)(b_blk * (4 * A_) + 4 * a_blk)) * HW_ + hw;
    const float4 txv = *reinterpret_cast<const float4*>(reg_map + reg_base);
    const float4 tyv = *reinterpret_cast<const float4*>(reg_map + reg_base + HW_);
    const float4 twv = *reinterpret_cast<const float4*>(reg_map + reg_base + 2 * HW_);
    const float4 thv = *reinterpret_cast<const float4*>(reg_map + reg_base + 3 * HW_);

    const float S    = 2048.0f;
    const float invS = 1.0f / 2048.0f;

    float vout[VEC * 9];

    const float* c0a = &c0v.x; const float* c1a = &c1v.x;
    const float* txa = &txv.x; const float* tya = &tyv.x;
    const float* twa = &twv.x; const float* tha = &thv.x;

    #pragma unroll
    for (int e = 0; e < VEC; e++) {
        const float4 anc = s_anc[w0 + e];
        const float acx = anc.x, acy = anc.y, aw = anc.z, ah = anc.w;

        const float fg = 1.0f / (1.0f + expf(c0a[e] - c1a[e]));  // sigmoid(c1-c0)

        const float cx = (txa[e] * aw + acx) * S;
        const float cy = (tya[e] * ah + acy) * S;
        const float wd = expf(twa[e]) * aw * S;
        const float hd = expf(tha[e]) * ah * S;

        const float ltx = cx - 0.5f * wd;
        const float lty = cy - 0.5f * hd;
        const float rbx = cx + 0.5f * wd;
        const float rby = cy + 0.5f * hd;

        const bool valid = (fg > 0.7f) & (ltx >= 0.0f) & (lty >= 0.0f)
                         & (rbx <= S)  & (rby <= S);
        const float m  = valid ? 1.0f : 0.0f;
        const float mS = m * invS;

        vout[e * 9 + 0] = ltx * m;
        vout[e * 9 + 1] = lty * m;
        vout[e * 9 + 2] = rbx * m;
        vout[e * 9 + 3] = rby * m;
        vout[e * 9 + 4] = cx * mS;
        vout[e * 9 + 5] = cy * mS;
        vout[e * 9 + 6] = wd * mS;
        vout[e * 9 + 7] = hd * mS;
        vout[e * 9 + 8] = m;
    }

    // Stage: 9 x STS.128 (byte offset tid*144, 16B aligned, conflict-free)
    {
        float4* sp = s_out + tid * 9;
        const float4* vp = reinterpret_cast<const float4*>(vout);
        #pragma unroll
        for (int j = 0; j < 9; j++) sp[j] = vp[j];
    }
    __syncthreads();

    // TMA bulk store: 36 KB contiguous smem -> gmem, issued by one thread.
    if (tid == 0) {
        // Order generic-proxy STS before async-proxy TMA read
        asm volatile("fence.proxy.async.shared::cta;" ::: "memory");
        float* gdst = out + (size_t)blockIdx.x * OUT_F_PER_BLK;
        asm volatile(
            "cp.async.bulk.global.shared::cta.bulk_group [%0], [%1], %2;"
            :: "l"(gdst), "r"(smem_u32(s_out)), "n"(OUT_BYTES_PER_BLK)
            : "memory");
        asm volatile("cp.async.bulk.commit_group;" ::: "memory");
        // smem must remain valid until TMA has read it
        asm volatile("cp.async.bulk.wait_group 0;" ::: "memory");
    }
}

extern "C" void kernel_launch(void* const* d_in, const int* in_sizes, int n_in,
                              void* d_out, int out_size)
{
    const float* cla_map = (const float*)d_in[0];
    const float* reg_map = (const float*)d_in[1];
    const float* anchor  = (const float*)d_in[2];
    float*       out     = (float*)d_out;

    const int grid = NTOT / ELEMS_PER_BLK;   // 2304
    proposal_target_kernel<<<grid, TPB>>>(cla_map, reg_map, anchor, out);
}